// round 15
// baseline (speedup 1.0000x reference)
#include <cuda_runtime.h>
#include <cuda_fp16.h>
#include <math.h>
#include <stdint.h>

// ---------------------------------------------------------------------------
// Problem constants
// ---------------------------------------------------------------------------
#define BB   8
#define NQL  1024
#define DD   2048
#define HH   16
#define DHH  128
#define FFD  8192
#define RR   16
#define MQ   (BB*NQL)
#define LORA_SCALE 1.0f

// ---------------------------------------------------------------------------
// Scratch (device globals)
// ---------------------------------------------------------------------------
__device__ __align__(256) float g_rrms[MQ];
__device__ __align__(256) float g_xbar[BB*DD];
__device__ __align__(256) float g_logits[BB*4];
__device__ __align__(256) float g_gate[BB*4];
__device__ __align__(256) float g_S[(long long)BB*HH*NQL*1024];   // fp32 scores
__device__ __align__(256) float g_delta[(long long)MQ*DD];
__device__ __align__(256) float g_x1[(long long)MQ*DD];
__device__ __align__(256) float g_G[(long long)MQ*FFD];
__device__ __align__(256) float g_U[(long long)MQ*FFD];
__device__ __align__(256) float g_T[(long long)MQ*DD];
// fp16 operand buffers
__device__ __align__(256) __half g_hZ[(long long)50331648];       // z_a,z_v,z_av,x_q
__device__ __align__(256) __half g_hW[(long long)4*3*DD*DD];      // WqT,WkT,WvT,WoT
__device__ __align__(256) __half g_hM[(long long)3*DD*FFD];       // gateT,upT,downT
__device__ __align__(256) __half g_hLa[491520];                   // LoRA transposed
__device__ __align__(256) __half g_hQ[(long long)MQ*DD];
__device__ __align__(256) __half g_hK[(long long)MQ*DD];
__device__ __align__(256) __half g_hV[(long long)MQ*DD];
__device__ __align__(256) __half g_hVt[(long long)MQ*DD];
__device__ __align__(256) __half g_hO[(long long)MQ*DD];
__device__ __align__(256) __half g_hH[(long long)MQ*DD];
__device__ __align__(256) __half g_hP[(long long)BB*HH*NQL*1024];
__device__ __align__(256) __half g_hXd[(long long)MQ*FFD];
__device__ __align__(256) __half g_hLt[(long long)MQ*RR];

// ---------------------------------------------------------------------------
// Helpers
// ---------------------------------------------------------------------------
__device__ __forceinline__ void mma_f16(float& c0, float& c1, float& c2, float& c3,
                                        unsigned a0, unsigned a1, unsigned a2, unsigned a3,
                                        unsigned b0, unsigned b1)
{
    asm volatile(
        "mma.sync.aligned.m16n8k16.row.col.f32.f16.f16.f32 "
        "{%0,%1,%2,%3}, {%4,%5,%6,%7}, {%8,%9}, {%0,%1,%2,%3};"
        : "+f"(c0), "+f"(c1), "+f"(c2), "+f"(c3)
        : "r"(a0), "r"(a1), "r"(a2), "r"(a3), "r"(b0), "r"(b1));
}

__device__ __forceinline__ void ldsm4(unsigned& r0, unsigned& r1, unsigned& r2, unsigned& r3,
                                      unsigned addr)
{
    asm volatile("ldmatrix.sync.aligned.m8n8.x4.shared.b16 {%0,%1,%2,%3}, [%4];"
                 : "=r"(r0), "=r"(r1), "=r"(r2), "=r"(r3) : "r"(addr));
}

__device__ __forceinline__ void cp16(void* dst_smem, const void* src, bool pred)
{
    unsigned d = (unsigned)__cvta_generic_to_shared(dst_smem);
    int sz = pred ? 16 : 0;
    asm volatile("cp.async.cg.shared.global [%0], [%1], 16, %2;\n"
                 :: "r"(d), "l"(src), "r"(sz));
}
__device__ __forceinline__ void cp_commit() { asm volatile("cp.async.commit_group;\n"); }
template <int N>
__device__ __forceinline__ void cp_wait() { asm volatile("cp.async.wait_group %0;\n" :: "n"(N)); }

// ---------------------------------------------------------------------------
// fp16 tensor-core strided-batched GEMM, fp32 accumulate, ldmatrix frags.
// A [M,K] row-major fp16 (lda). B [N,K] row-major fp16 (ldb) -> used as B^T.
// C = rowscale * (alpha * A@B^T + bias) + beta*C ; OC=1 -> fp16 C, OC=0 -> fp32 C.
// Block 128x128x32, 2-stage cp.async; 4 warps (2Mx2N), warp tile 64x64.
// ---------------------------------------------------------------------------
#define NT 128
#define AST 40                       // halfs per row (32 + 8 pad): 80B rows
#define STG (128*AST)                // 5120 halfs per stage per operand

template <int OC>
__global__ __launch_bounds__(NT, 2)
void hgemm_k(int M, int N, int K,
             const __half* __restrict__ A, int lda, long long sA1, long long sA2,
             const __half* __restrict__ B, int ldb, long long sB1, long long sB2,
             void* __restrict__ Cv, int ldc, long long sC1, long long sC2,
             int zdiv, float alpha, float beta, const float* __restrict__ bias,
             const float* __restrict__ rowscale, int rs_shift, int rs_mul, int rs_off)
{
    __shared__ __align__(32) __half sm[4*STG];   // A0,A1,B0,B1
    __half* As = sm;
    __half* Bs = sm + 2*STG;

    int z = blockIdx.z;
    A += (long long)(z / zdiv) * sA1 + (long long)(z % zdiv) * sA2;
    B += (long long)(z / zdiv) * sB1 + (long long)(z % zdiv) * sB2;
    float* Cf = (float*)Cv + ((long long)(z / zdiv) * sC1 + (long long)(z % zdiv) * sC2);
    __half* Ch = (__half*)Cv + ((long long)(z / zdiv) * sC1 + (long long)(z % zdiv) * sC2);

    int bm = blockIdx.y * 128;
    int bn = blockIdx.x * 128;
    int tid  = threadIdx.x;
    int lane = tid & 31;
    int wid  = tid >> 5;
    int wm = (wid & 1) * 64;
    int wn = (wid >> 1) * 64;

    float acc[4][8][4];
#pragma unroll
    for (int i = 0; i < 4; i++)
#pragma unroll
        for (int j = 0; j < 8; j++)
#pragma unroll
            for (int q = 0; q < 4; q++) acc[i][j][q] = 0.f;

    int ktiles = (K + 31) >> 5;

    auto load_tile = [&](int kt, int stage) {
        int k0 = kt * 32;
#pragma unroll
        for (int i = 0; i < 4; i++) {
            int idx = tid + i * NT;        // 0..511
            int row = idx >> 2;
            int c   = idx & 3;
            int gk  = k0 + c * 8;
            {
                int gm = bm + row;
                cp16(&As[stage*STG + row*AST + c*8],
                     A + (long long)gm * lda + gk, (gm < M) && (gk < K));
            }
            {
                int gn = bn + row;
                cp16(&Bs[stage*STG + row*AST + c*8],
                     B + (long long)gn * ldb + gk, (gn < N) && (gk < K));
            }
        }
        cp_commit();
    };

    load_tile(0, 0);

    // precomputed ldmatrix lane-address components (in halfs)
    int a_row = wm + (lane & 15);          // + mi*16
    int a_col = (lane >> 4) * 8;           // + kk
    int b_row = wn + ((lane >> 4) * 8) + (lane & 7);   // + p*16
    int b_col = ((lane >> 3) & 1) * 8;     // + kk

    for (int kt = 0; kt < ktiles; kt++) {
        int cur = kt & 1;
        if (kt + 1 < ktiles) {
            load_tile(kt + 1, (kt + 1) & 1);
            cp_wait<1>();
        } else {
            cp_wait<0>();
        }
        __syncthreads();

        unsigned abase = (unsigned)__cvta_generic_to_shared(As + cur * STG);
        unsigned bbase = (unsigned)__cvta_generic_to_shared(Bs + cur * STG);

#pragma unroll
        for (int ks = 0; ks < 2; ks++) {
            int kk = ks * 16;
            unsigned afr[4][4];
#pragma unroll
            for (int mi = 0; mi < 4; mi++) {
                unsigned addr = abase + (unsigned)(((a_row + mi * 16) * AST + kk + a_col) * 2);
                ldsm4(afr[mi][0], afr[mi][1], afr[mi][2], afr[mi][3], addr);
            }
            unsigned bfr[8][2];
#pragma unroll
            for (int p = 0; p < 4; p++) {
                unsigned addr = bbase + (unsigned)(((b_row + p * 16) * AST + kk + b_col) * 2);
                ldsm4(bfr[2*p][0], bfr[2*p][1], bfr[2*p+1][0], bfr[2*p+1][1], addr);
            }
#pragma unroll
            for (int mi = 0; mi < 4; mi++)
#pragma unroll
                for (int ni = 0; ni < 8; ni++)
                    mma_f16(acc[mi][ni][0], acc[mi][ni][1], acc[mi][ni][2], acc[mi][ni][3],
                            afr[mi][0], afr[mi][1], afr[mi][2], afr[mi][3],
                            bfr[ni][0], bfr[ni][1]);
        }
        __syncthreads();
    }

    // ---- epilogue ----
#pragma unroll
    for (int mi = 0; mi < 4; mi++) {
        int r0 = bm + wm + mi * 16 + (lane >> 2);
#pragma unroll
        for (int ni = 0; ni < 8; ni++) {
            int cbase = bn + wn + ni * 8 + 2 * (lane & 3);
#pragma unroll
            for (int q = 0; q < 4; q++) {
                int gm = r0 + ((q >> 1) ? 8 : 0);
                int gn = cbase + (q & 1);
                if (gm >= M || gn >= N) continue;
                float v = alpha * acc[mi][ni][q];
                if (bias) v += bias[gn];
                if (rowscale) v *= rowscale[(gm >> rs_shift) * rs_mul + rs_off];
                long long off = (long long)gm * ldc + gn;
                if (OC) {
                    Ch[off] = __float2half_rn(v);
                } else {
                    if (beta != 0.f) v += beta * Cf[off];
                    Cf[off] = v;
                }
            }
        }
    }
}

// ---------------------------------------------------------------------------
// Conversions
// ---------------------------------------------------------------------------
__global__ void f2h_copy_k(const float* __restrict__ src, __half* __restrict__ dst, long long n4)
{
    long long i = (long long)blockIdx.x * blockDim.x + threadIdx.x;
    if (i >= n4) return;
    float4 v = reinterpret_cast<const float4*>(src)[i];
    __half2 a = __floats2half2_rn(v.x, v.y);
    __half2 b = __floats2half2_rn(v.z, v.w);
    reinterpret_cast<__half2*>(dst)[2*i]   = a;
    reinterpret_cast<__half2*>(dst)[2*i+1] = b;
}

// src fp32 [R,C] -> dst fp16 [C,R], batched
__global__ void transpose_f2h_k(const float* __restrict__ src, __half* __restrict__ dst,
                                int R, int C, long long bs)
{
    __shared__ float t[32][33];
    src += (long long)blockIdx.z * bs;
    dst += (long long)blockIdx.z * bs;
    int r0 = blockIdx.y * 32, c0 = blockIdx.x * 32;
    int tx = threadIdx.x, ty = threadIdx.y;
#pragma unroll
    for (int i = 0; i < 32; i += 8) {
        int rr = r0 + ty + i, cc = c0 + tx;
        t[ty + i][tx] = (rr < R && cc < C) ? src[(long long)rr * C + cc] : 0.f;
    }
    __syncthreads();
#pragma unroll
    for (int i = 0; i < 32; i += 8) {
        int cc = c0 + ty + i, rr = r0 + tx;
        if (cc < C && rr < R) dst[(long long)cc * R + rr] = __float2half_rn(t[tx][ty + i]);
    }
}

// src fp16 [R,C] -> dst fp16 [C,R], batched
__global__ void transpose_h_k(const __half* __restrict__ src, __half* __restrict__ dst,
                              int R, int C, long long bs)
{
    __shared__ __half t[32][33];
    src += (long long)blockIdx.z * bs;
    dst += (long long)blockIdx.z * bs;
    int r0 = blockIdx.y * 32, c0 = blockIdx.x * 32;
    int tx = threadIdx.x, ty = threadIdx.y;
#pragma unroll
    for (int i = 0; i < 32; i += 8) {
        int rr = r0 + ty + i, cc = c0 + tx;
        t[ty + i][tx] = (rr < R && cc < C) ? src[(long long)rr * C + cc] : __half(0.f);
    }
    __syncthreads();
#pragma unroll
    for (int i = 0; i < 32; i += 8) {
        int cc = c0 + ty + i, rr = r0 + tx;
        if (cc < C && rr < R) dst[(long long)cc * R + rr] = t[tx][ty + i];
    }
}

// ---------------------------------------------------------------------------
// Router / norm / softmax / elementwise
// ---------------------------------------------------------------------------
__global__ void rowrms_k(const float* __restrict__ X, float* __restrict__ rrms, int ncols)
{
    int row = blockIdx.x;
    const float* p = X + (long long)row * ncols;
    __shared__ float red[256];
    float s = 0.f;
    for (int c = threadIdx.x; c < ncols; c += 256) { float v = p[c]; s += v * v; }
    red[threadIdx.x] = s; __syncthreads();
    for (int st = 128; st > 0; st >>= 1) {
        if (threadIdx.x < st) red[threadIdx.x] += red[threadIdx.x + st];
        __syncthreads();
    }
    if (threadIdx.x == 0) rrms[row] = rsqrtf(red[0] / ncols + 1e-6f);
}

__global__ void xbar_k(const float* __restrict__ X, const float* __restrict__ rrms,
                       const float* __restrict__ w, float* __restrict__ xbar)
{
    int idx = blockIdx.x * blockDim.x + threadIdx.x;
    if (idx >= BB * DD) return;
    int b = idx / DD, d = idx % DD;
    const float* xp = X + (long long)b * NQL * DD + d;
    const float* rp = rrms + b * NQL;
    float s = 0.f;
    for (int n = 0; n < NQL; n++) s += xp[(long long)n * DD] * rp[n];
    xbar[idx] = w[d] * s * (1.f / NQL);
}

__global__ void router_logits_k(const float* __restrict__ xbar, const float* __restrict__ W,
                                const float* __restrict__ bias, float* __restrict__ logits)
{
    int b = blockIdx.x >> 2, e = blockIdx.x & 3;
    __shared__ float red[256];
    float s = 0.f;
    for (int k = threadIdx.x; k < DD; k += 256) s += xbar[b * DD + k] * W[k * 4 + e];
    red[threadIdx.x] = s; __syncthreads();
    for (int st = 128; st > 0; st >>= 1) {
        if (threadIdx.x < st) red[threadIdx.x] += red[threadIdx.x + st];
        __syncthreads();
    }
    if (threadIdx.x == 0) logits[b * 4 + e] = red[0] + bias[e];
}

__global__ void gate_k(const float* __restrict__ logits, float* __restrict__ gate)
{
    int b = threadIdx.x;
    if (b >= BB) return;
    float l[4]; float mx = -1e30f;
    for (int e = 0; e < 4; e++) { l[e] = logits[b * 4 + e]; mx = fmaxf(mx, l[e]); }
    float s = 0.f;
    for (int e = 0; e < 4; e++) { l[e] = expf(l[e] - mx); s += l[e]; }
    for (int e = 0; e < 4; e++) l[e] /= s;
    int i1 = 0;
    for (int e = 1; e < 4; e++) if (l[e] > l[i1]) i1 = e;
    int i2 = -1;
    for (int e = 0; e < 4; e++) if (e != i1 && (i2 < 0 || l[e] > l[i2])) i2 = e;
    float denom = l[i1] + l[i2] + 1e-10f;
    float g[4] = {0.f, 0.f, 0.f, 0.f};
    g[i1] = l[i1] / denom;
    g[i2] = l[i2] / denom;
    for (int e = 0; e < 4; e++) gate[b * 4 + e] = g[e];
}

// softmax over fp32 scores -> fp16 probabilities
__global__ void softmax_h_k(const float* __restrict__ S, __half* __restrict__ P, int ncols)
{
    int row = blockIdx.x;
    const float* p = S + (long long)row * ncols;
    __half* q = P + (long long)row * ncols;
    __shared__ float sm[1024];
    __shared__ float red[256];
    int tid = threadIdx.x;
    float mx = -1e30f;
    for (int c = tid; c < ncols; c += 256) { float v = p[c]; sm[c] = v; mx = fmaxf(mx, v); }
    red[tid] = mx; __syncthreads();
    for (int st = 128; st > 0; st >>= 1) {
        if (tid < st) red[tid] = fmaxf(red[tid], red[tid + st]);
        __syncthreads();
    }
    mx = red[0]; __syncthreads();
    float sum = 0.f;
    for (int c = tid; c < ncols; c += 256) { float e = __expf(sm[c] - mx); sm[c] = e; sum += e; }
    red[tid] = sum; __syncthreads();
    for (int st = 128; st > 0; st >>= 1) {
        if (tid < st) red[tid] += red[tid + st];
        __syncthreads();
    }
    float inv = 1.f / red[0];
    __syncthreads();
    for (int c = tid; c < ncols; c += 256) q[c] = __float2half_rn(sm[c] * inv);
}

__global__ void x1_k(const float* __restrict__ xq, const float* __restrict__ delta,
                     const float* __restrict__ alpha1, float* __restrict__ x1)
{
    int idx = blockIdx.x * blockDim.x + threadIdx.x;
    if (idx >= MQ * DD) return;
    float s = 1.f / (1.f + expf(-alpha1[0]));
    x1[idx] = xq[idx] + s * delta[idx];
}

__global__ void rmsnorm_h_k(const float* __restrict__ X, const float* __restrict__ w,
                            __half* __restrict__ Y, int ncols)
{
    int row = blockIdx.x;
    const float* p = X + (long long)row * ncols;
    __half* q = Y + (long long)row * ncols;
    __shared__ float red[256];
    float s = 0.f;
    for (int c = threadIdx.x; c < ncols; c += 256) { float v = p[c]; s += v * v; }
    red[threadIdx.x] = s; __syncthreads();
    for (int st = 128; st > 0; st >>= 1) {
        if (threadIdx.x < st) red[threadIdx.x] += red[threadIdx.x + st];
        __syncthreads();
    }
    float scale = rsqrtf(red[0] / ncols + 1e-6f);
    __syncthreads();
    for (int c = threadIdx.x; c < ncols; c += 256) q[c] = __float2half_rn(w[c] * p[c] * scale);
}

__global__ void silu_add_h_k(const float* __restrict__ G, const float* __restrict__ U,
                             __half* __restrict__ Xd, long long n)
{
    long long idx = (long long)blockIdx.x * blockDim.x + threadIdx.x;
    if (idx >= n) return;
    float g = G[idx];
    Xd[idx] = __float2half_rn(g / (1.f + expf(-g)) + U[idx]);
}

__global__ void out_k(const float* __restrict__ x1, const float* __restrict__ T,
                      const float* __restrict__ alpha2, float* __restrict__ out)
{
    int idx = blockIdx.x * blockDim.x + threadIdx.x;
    if (idx >= MQ * DD) return;
    float s = 1.f / (1.f + expf(-alpha2[0]));
    out[idx] = x1[idx] + s * T[idx];
}

// ---------------------------------------------------------------------------
// Host helpers
// ---------------------------------------------------------------------------
static void hgemm(int OC, int M, int N, int K,
                  const __half* A, int lda, long long sA1, long long sA2,
                  const __half* B, int ldb, long long sB1, long long sB2,
                  void* C, int ldc, long long sC1, long long sC2,
                  int Z, int zdiv, float alpha, float beta, const float* bias,
                  const float* rowscale = nullptr, int rs_shift = 0, int rs_mul = 0, int rs_off = 0)
{
    dim3 grid((N + 127) / 128, (M + 127) / 128, Z);
    if (OC)
        hgemm_k<1><<<grid, NT>>>(M, N, K, A, lda, sA1, sA2, B, ldb, sB1, sB2,
                                 C, ldc, sC1, sC2, zdiv, alpha, beta, bias,
                                 rowscale, rs_shift, rs_mul, rs_off);
    else
        hgemm_k<0><<<grid, NT>>>(M, N, K, A, lda, sA1, sA2, B, ldb, sB1, sB2,
                                 C, ldc, sC1, sC2, zdiv, alpha, beta, bias,
                                 rowscale, rs_shift, rs_mul, rs_off);
}

template <typename T>
static T* sym(const void* s)
{
    void* p = nullptr;
    cudaGetSymbolAddress(&p, (const void*)s);
    return (T*)p;
}

static void f2h_copy(const float* src, __half* dst, long long n)
{
    long long n4 = n / 4;
    f2h_copy_k<<<(int)((n4 + 255) / 256), 256>>>(src, dst, n4);
}

static void transpose_f2h(const float* src, __half* dst, int R, int C, int batch)
{
    dim3 grid((C + 31) / 32, (R + 31) / 32, batch);
    transpose_f2h_k<<<grid, dim3(32, 8)>>>(src, dst, R, C, (long long)R * C);
}

static void transpose_h(const __half* src, __half* dst, int R, int C, int batch)
{
    dim3 grid((C + 31) / 32, (R + 31) / 32, batch);
    transpose_h_k<<<grid, dim3(32, 8)>>>(src, dst, R, C, (long long)R * C);
}

// ---------------------------------------------------------------------------
// kernel_launch
// ---------------------------------------------------------------------------
extern "C" void kernel_launch(void* const* d_in, const int* in_sizes, int n_in,
                              void* d_out, int out_size)
{
    const float* x_q      = (const float*)d_in[0];
    const float* z_a      = (const float*)d_in[1];
    const float* z_v      = (const float*)d_in[2];
    const float* z_av     = (const float*)d_in[3];
    const float* ln1_w    = (const float*)d_in[4];
    const float* router_W = (const float*)d_in[5];
    const float* router_b = (const float*)d_in[6];
    const float* Wq       = (const float*)d_in[7];
    const float* bq       = (const float*)d_in[8];
    const float* Wk       = (const float*)d_in[9];
    const float* bk       = (const float*)d_in[10];
    const float* Wv       = (const float*)d_in[11];
    const float* bv       = (const float*)d_in[12];
    const float* Wo       = (const float*)d_in[13];
    const float* bo       = (const float*)d_in[14];
    const float* alpha1   = (const float*)d_in[15];
    const float* alpha2   = (const float*)d_in[16];
    const float* ln2_w    = (const float*)d_in[17];
    const float* gate_w   = (const float*)d_in[18];
    const float* up_w     = (const float*)d_in[19];
    const float* down_w   = (const float*)d_in[20];
    const float* la_gA    = (const float*)d_in[21];
    const float* la_gB    = (const float*)d_in[22];
    const float* la_uA    = (const float*)d_in[23];
    const float* la_uB    = (const float*)d_in[24];
    const float* la_dA    = (const float*)d_in[25];
    const float* la_dB    = (const float*)d_in[26];
    float* out = (float*)d_out;

    float* pRrms  = sym<float>(&g_rrms);
    float* pXbar  = sym<float>(&g_xbar);
    float* pLog   = sym<float>(&g_logits);
    float* pGate  = sym<float>(&g_gate);
    float* pS     = sym<float>(&g_S);
    float* pDelta = sym<float>(&g_delta);
    float* pX1    = sym<float>(&g_x1);
    float* pG     = sym<float>(&g_G);
    float* pU     = sym<float>(&g_U);
    float* pT     = sym<float>(&g_T);
    __half* hZ   = sym<__half>(&g_hZ);
    __half* hW   = sym<__half>(&g_hW);
    __half* hM   = sym<__half>(&g_hM);
    __half* hLa  = sym<__half>(&g_hLa);
    __half* hQ   = sym<__half>(&g_hQ);
    __half* hK   = sym<__half>(&g_hK);
    __half* hV   = sym<__half>(&g_hV);
    __half* hVt  = sym<__half>(&g_hVt);
    __half* hO   = sym<__half>(&g_hO);
    __half* hH   = sym<__half>(&g_hH);
    __half* hP   = sym<__half>(&g_hP);
    __half* hXd  = sym<__half>(&g_hXd);
    __half* hLt  = sym<__half>(&g_hLt);

    const long long WSZ = (long long)3 * DD * DD;
    __half* tWqT = hW;            __half* tWkT = hW + WSZ;
    __half* tWvT = hW + 2 * WSZ;  __half* tWoT = hW + 3 * WSZ;
    const long long MSZ = (long long)DD * FFD;
    __half* tGwT = hM; __half* tUwT = hM + MSZ; __half* tDwT = hM + 2 * MSZ;
    const long long ZA = (long long)BB * 512 * DD;
    const long long ZAV = (long long)BB * 1024 * DD;
    __half* hZa  = hZ;
    __half* hZv  = hZ + ZA;
    __half* hZav = hZ + 2 * ZA;
    __half* hXq  = hZ + 2 * ZA + ZAV;
    __half* tgA = hLa;             __half* tgB = tgA + DD * RR;
    __half* tuA = tgB + RR * FFD;  __half* tuB = tuA + DD * RR;
    __half* tdA = tuB + RR * FFD;  __half* tdB = tdA + FFD * RR;

    // ---- operand conversions ----
    transpose_f2h(Wq, tWqT, DD, DD, 3);
    transpose_f2h(Wk, tWkT, DD, DD, 3);
    transpose_f2h(Wv, tWvT, DD, DD, 3);
    transpose_f2h(Wo, tWoT, DD, DD, 3);
    transpose_f2h(gate_w, tGwT, DD, FFD, 1);
    transpose_f2h(up_w,   tUwT, DD, FFD, 1);
    transpose_f2h(down_w, tDwT, FFD, DD, 1);
    transpose_f2h(la_gA, tgA, DD, RR, 1);
    transpose_f2h(la_gB, tgB, RR, FFD, 1);
    transpose_f2h(la_uA, tuA, DD, RR, 1);
    transpose_f2h(la_uB, tuB, RR, FFD, 1);
    transpose_f2h(la_dA, tdA, FFD, RR, 1);
    transpose_f2h(la_dB, tdB, RR, DD, 1);
    f2h_copy(z_a,  hZa,  ZA);
    f2h_copy(z_v,  hZv,  ZA);
    f2h_copy(z_av, hZav, ZAV);
    f2h_copy(x_q,  hXq,  ZAV);

    const int EW_B = (MQ * DD + 255) / 256;

    // ---- router (fp32 path on original inputs) ----
    rowrms_k<<<MQ, 256>>>(x_q, pRrms, DD);
    xbar_k<<<(BB * DD + 255) / 256, 256>>>(x_q, pRrms, ln1_w, pXbar);
    router_logits_k<<<BB * 4, 256>>>(pXbar, router_W, router_b, pLog);
    gate_k<<<1, 32>>>(pLog, pGate);

    // ---- experts ----
    const __half* hzs[3] = {hZa, hZv, hZav};
    const int     nks[3] = {512, 512, 1024};
    const float att_scale = 0.08838834764831843f;  // 1/sqrt(128)

    for (int e = 0; e < 3; e++) {
        const __half* hz = hzs[e];
        int NK = nks[e];
        int MZ = BB * NK;

        hgemm(1, MQ, DD, DD, hXq, DD, 0, 0, tWqT + (long long)e * DD * DD, DD, 0, 0,
              hQ, DD, 0, 0, 1, 1, 1.f, 0.f, bq + e * DD);
        hgemm(1, MZ, DD, DD, hz, DD, 0, 0, tWkT + (long long)e * DD * DD, DD, 0, 0,
              hK, DD, 0, 0, 1, 1, 1.f, 0.f, bk + e * DD);
        hgemm(1, MZ, DD, DD, hz, DD, 0, 0, tWvT + (long long)e * DD * DD, DD, 0, 0,
              hV, DD, 0, 0, 1, 1, 1.f, 0.f, bv + e * DD);

        transpose_h(hV, hVt, NK, DD, BB);

        hgemm(0, NQL, NK, DHH,
              hQ, DD, (long long)NQL * DD, DHH,
              hK, DD, (long long)NK * DD, DHH,
              pS, NK, (long long)HH * NQL * NK, (long long)NQL * NK,
              BB * HH, HH, att_scale, 0.f, nullptr);

        softmax_h_k<<<BB * HH * NQL, 256>>>(pS, hP, NK);

        hgemm(1, NQL, DHH, NK,
              hP, NK, (long long)HH * NQL * NK, (long long)NQL * NK,
              hVt, NK, (long long)DD * NK, (long long)DHH * NK,
              hO, DD, (long long)NQL * DD, DHH,
              BB * HH, HH, 1.f, 0.f, nullptr);

        hgemm(0, MQ, DD, DD, hO, DD, 0, 0, tWoT + (long long)e * DD * DD, DD, 0, 0,
              pDelta, DD, 0, 0, 1, 1, 1.f, (e == 0) ? 0.f : 1.f, bo + e * DD,
              pGate, 10, 4, e);
    }

    // ---- x1 = x_q + sigmoid(alpha1)*delta ----
    x1_k<<<EW_B, 256>>>(x_q, pDelta, alpha1, pX1);

    // ---- MLP with LoRA ----
    rmsnorm_h_k<<<MQ, 256>>>(pX1, ln2_w, hH, DD);

    // gate path
    hgemm(0, MQ, FFD, DD, hH, DD, 0, 0, tGwT, DD, 0, 0, pG, FFD, 0, 0, 1, 1, 1.f, 0.f, nullptr);
    hgemm(1, MQ, RR, DD, hH, DD, 0, 0, tgA, DD, 0, 0, hLt, RR, 0, 0, 1, 1, 1.f, 0.f, nullptr);
    hgemm(0, MQ, FFD, RR, hLt, RR, 0, 0, tgB, RR, 0, 0, pG, FFD, 0, 0, 1, 1, LORA_SCALE, 1.f, nullptr);

    // up path
    hgemm(0, MQ, FFD, DD, hH, DD, 0, 0, tUwT, DD, 0, 0, pU, FFD, 0, 0, 1, 1, 1.f, 0.f, nullptr);
    hgemm(1, MQ, RR, DD, hH, DD, 0, 0, tuA, DD, 0, 0, hLt, RR, 0, 0, 1, 1, 1.f, 0.f, nullptr);
    hgemm(0, MQ, FFD, RR, hLt, RR, 0, 0, tuB, RR, 0, 0, pU, FFD, 0, 0, 1, 1, LORA_SCALE, 1.f, nullptr);

    // x_down = silu(gate) + up -> fp16
    {
        long long n = (long long)MQ * FFD;
        silu_add_h_k<<<(int)((n + 255) / 256), 256>>>(pG, pU, hXd, n);
    }

    // down path
    hgemm(0, MQ, DD, FFD, hXd, FFD, 0, 0, tDwT, FFD, 0, 0, pT, DD, 0, 0, 1, 1, 1.f, 0.f, nullptr);
    hgemm(1, MQ, RR, FFD, hXd, FFD, 0, 0, tdA, FFD, 0, 0, hLt, RR, 0, 0, 1, 1, 1.f, 0.f, nullptr);
    hgemm(0, MQ, DD, RR, hLt, RR, 0, 0, tdB, RR, 0, 0, pT, DD, 0, 0, 1, 1, LORA_SCALE, 1.f, nullptr);

    // out = x1 + sigmoid(alpha2)*mlp_out
    out_k<<<EW_B, 256>>>(pX1, pT, alpha2, out);
}

// round 16
// speedup vs baseline: 1.1724x; 1.1724x over previous
#include <cuda_runtime.h>
#include <cuda_fp16.h>
#include <math.h>
#include <stdint.h>

// ---------------------------------------------------------------------------
// Problem constants
// ---------------------------------------------------------------------------
#define BB   8
#define NQL  1024
#define DD   2048
#define HH   16
#define DHH  128
#define FFD  8192
#define RR   16
#define MQ   (BB*NQL)
#define LORA_SCALE 1.0f

// ---------------------------------------------------------------------------
// Scratch (device globals)
// ---------------------------------------------------------------------------
__device__ __align__(256) float g_rrms[MQ];
__device__ __align__(256) float g_xbar[BB*DD];
__device__ __align__(256) float g_logits[BB*4];
__device__ __align__(256) float g_gate[BB*4];
__device__ __align__(256) float g_delta[(long long)MQ*DD];
__device__ __align__(256) float g_x1[(long long)MQ*DD];
__device__ __align__(256) float g_G[(long long)MQ*FFD];
__device__ __align__(256) float g_U[(long long)MQ*FFD];
__device__ __align__(256) float g_T[(long long)MQ*DD];
// fp16 operand buffers
__device__ __align__(256) __half g_hZ[(long long)50331648];       // z_a,z_v,z_av,x_q
__device__ __align__(256) __half g_hW[(long long)4*3*DD*DD];      // WqT,WkT,WvT,WoT
__device__ __align__(256) __half g_hM[(long long)3*DD*FFD];       // gateT,upT,downT
__device__ __align__(256) __half g_hLa[491520];                   // LoRA transposed
__device__ __align__(256) __half g_hQ[(long long)MQ*DD];
__device__ __align__(256) __half g_hK[(long long)MQ*DD];
__device__ __align__(256) __half g_hV[(long long)MQ*DD];
__device__ __align__(256) __half g_hVt[(long long)MQ*DD];
__device__ __align__(256) __half g_hO[(long long)MQ*DD];
__device__ __align__(256) __half g_hH[(long long)MQ*DD];
__device__ __align__(256) __half g_hP[(long long)BB*HH*NQL*1024]; // fp16 scores/probs (in-place)
__device__ __align__(256) __half g_hXd[(long long)MQ*FFD];
__device__ __align__(256) __half g_hLt[(long long)MQ*RR];

// ---------------------------------------------------------------------------
// Helpers
// ---------------------------------------------------------------------------
__device__ __forceinline__ void mma_f16(float& c0, float& c1, float& c2, float& c3,
                                        unsigned a0, unsigned a1, unsigned a2, unsigned a3,
                                        unsigned b0, unsigned b1)
{
    asm volatile(
        "mma.sync.aligned.m16n8k16.row.col.f32.f16.f16.f32 "
        "{%0,%1,%2,%3}, {%4,%5,%6,%7}, {%8,%9}, {%0,%1,%2,%3};"
        : "+f"(c0), "+f"(c1), "+f"(c2), "+f"(c3)
        : "r"(a0), "r"(a1), "r"(a2), "r"(a3), "r"(b0), "r"(b1));
}

__device__ __forceinline__ void ldsm4(unsigned& r0, unsigned& r1, unsigned& r2, unsigned& r3,
                                      unsigned addr)
{
    asm volatile("ldmatrix.sync.aligned.m8n8.x4.shared.b16 {%0,%1,%2,%3}, [%4];"
                 : "=r"(r0), "=r"(r1), "=r"(r2), "=r"(r3) : "r"(addr));
}

__device__ __forceinline__ void cp16(void* dst_smem, const void* src, bool pred)
{
    unsigned d = (unsigned)__cvta_generic_to_shared(dst_smem);
    int sz = pred ? 16 : 0;
    asm volatile("cp.async.cg.shared.global [%0], [%1], 16, %2;\n"
                 :: "r"(d), "l"(src), "r"(sz));
}
__device__ __forceinline__ void cp_commit() { asm volatile("cp.async.commit_group;\n"); }
template <int N>
__device__ __forceinline__ void cp_wait() { asm volatile("cp.async.wait_group %0;\n" :: "n"(N)); }

// ---------------------------------------------------------------------------
// fp16 tensor-core strided-batched GEMM, fp32 accumulate, ldmatrix frags.
// A [M,K] row-major fp16 (lda). B [N,K] row-major fp16 (ldb) -> used as B^T.
// C = rowscale * (alpha * A@B^T + bias) + beta*C ; OC=1 -> fp16 C, OC=0 -> fp32 C.
// Block 128x128x32, 3-stage cp.async (one barrier per k-iter); 4 warps, 64x64.
// Requires N even.
// ---------------------------------------------------------------------------
#define NT 128
#define AST 40                       // halfs per row (32 + 8 pad): 80B rows
#define STG (128*AST)                // 5120 halfs per stage per operand
#define HG_SMEM (6*STG*2)            // 3 stages x (A+B) = 61440 B dynamic

template <int OC>
__global__ __launch_bounds__(NT, 2)
void hgemm_k(int M, int N, int K,
             const __half* __restrict__ A, int lda, long long sA1, long long sA2,
             const __half* __restrict__ B, int ldb, long long sB1, long long sB2,
             void* __restrict__ Cv, int ldc, long long sC1, long long sC2,
             int zdiv, float alpha, float beta, const float* __restrict__ bias,
             const float* __restrict__ rowscale, int rs_shift, int rs_mul, int rs_off)
{
    extern __shared__ __half sm[];               // [3 stages][A:STG | B:STG]
    __half* As = sm;                             // stage s at As + s*2*STG
    __half* Bs = sm + STG;                       // stage s at Bs + s*2*STG

    int z = blockIdx.z;
    A += (long long)(z / zdiv) * sA1 + (long long)(z % zdiv) * sA2;
    B += (long long)(z / zdiv) * sB1 + (long long)(z % zdiv) * sB2;
    float* Cf = (float*)Cv + ((long long)(z / zdiv) * sC1 + (long long)(z % zdiv) * sC2);
    __half* Ch = (__half*)Cv + ((long long)(z / zdiv) * sC1 + (long long)(z % zdiv) * sC2);

    int bm = blockIdx.y * 128;
    int bn = blockIdx.x * 128;
    int tid  = threadIdx.x;
    int lane = tid & 31;
    int wid  = tid >> 5;
    int wm = (wid & 1) * 64;
    int wn = (wid >> 1) * 64;

    float acc[4][8][4];
#pragma unroll
    for (int i = 0; i < 4; i++)
#pragma unroll
        for (int j = 0; j < 8; j++)
#pragma unroll
            for (int q = 0; q < 4; q++) acc[i][j][q] = 0.f;

    int ktiles = (K + 31) >> 5;

    auto load_tile = [&](int kt, int stage) {
        int k0 = kt * 32;
        __half* Ad = As + stage * 2 * STG;
        __half* Bd = Bs + stage * 2 * STG;
#pragma unroll
        for (int i = 0; i < 4; i++) {
            int idx = tid + i * NT;        // 0..511
            int row = idx >> 2;
            int c   = idx & 3;
            int gk  = k0 + c * 8;
            {
                int gm = bm + row;
                cp16(&Ad[row*AST + c*8],
                     A + (long long)gm * lda + gk, (gm < M) && (gk < K));
            }
            {
                int gn = bn + row;
                cp16(&Bd[row*AST + c*8],
                     B + (long long)gn * ldb + gk, (gn < N) && (gk < K));
            }
        }
        cp_commit();
    };

    load_tile(0, 0);
    if (ktiles > 1) load_tile(1, 1);

    // precomputed ldmatrix lane-address components (in halfs)
    int a_row = wm + (lane & 15);          // + mi*16
    int a_col = (lane >> 4) * 8;           // + kk
    int b_row = wn + ((lane >> 4) * 8) + (lane & 7);   // + p*16
    int b_col = ((lane >> 3) & 1) * 8;     // + kk

    int stage = 0;
    for (int kt = 0; kt < ktiles; kt++) {
        if (kt + 1 < ktiles) cp_wait<1>(); else cp_wait<0>();
        __syncthreads();

        unsigned abase = (unsigned)__cvta_generic_to_shared(As + stage * 2 * STG);
        unsigned bbase = (unsigned)__cvta_generic_to_shared(Bs + stage * 2 * STG);

#pragma unroll
        for (int ks = 0; ks < 2; ks++) {
            int kk = ks * 16;
            unsigned afr[4][4];
#pragma unroll
            for (int mi = 0; mi < 4; mi++) {
                unsigned addr = abase + (unsigned)(((a_row + mi * 16) * AST + kk + a_col) * 2);
                ldsm4(afr[mi][0], afr[mi][1], afr[mi][2], afr[mi][3], addr);
            }
            unsigned bfr[8][2];
#pragma unroll
            for (int p = 0; p < 4; p++) {
                unsigned addr = bbase + (unsigned)(((b_row + p * 16) * AST + kk + b_col) * 2);
                ldsm4(bfr[2*p][0], bfr[2*p][1], bfr[2*p+1][0], bfr[2*p+1][1], addr);
            }
#pragma unroll
            for (int mi = 0; mi < 4; mi++)
#pragma unroll
                for (int ni = 0; ni < 8; ni++)
                    mma_f16(acc[mi][ni][0], acc[mi][ni][1], acc[mi][ni][2], acc[mi][ni][3],
                            afr[mi][0], afr[mi][1], afr[mi][2], afr[mi][3],
                            bfr[ni][0], bfr[ni][1]);
        }

        // prefetch kt+2 into the stage last read at iteration kt-1 (all warps
        // passed this iteration's barrier after finishing those reads)
        if (kt + 2 < ktiles) {
            int st2 = stage + 2; if (st2 >= 3) st2 -= 3;
            load_tile(kt + 2, st2);
        }
        if (++stage == 3) stage = 0;
    }

    // ---- epilogue (paired stores; N even) ----
#pragma unroll
    for (int mi = 0; mi < 4; mi++) {
        int r0 = bm + wm + mi * 16 + (lane >> 2);
#pragma unroll
        for (int ni = 0; ni < 8; ni++) {
            int cb = bn + wn + ni * 8 + 2 * (lane & 3);
            if (cb >= N) continue;
            float b0 = bias ? bias[cb] : 0.f;
            float b1 = bias ? bias[cb + 1] : 0.f;
#pragma unroll
            for (int h = 0; h < 2; h++) {
                int gm = r0 + h * 8;
                if (gm >= M) continue;
                float v0 = alpha * acc[mi][ni][2*h]     + b0;
                float v1 = alpha * acc[mi][ni][2*h + 1] + b1;
                if (rowscale) {
                    float rs = rowscale[(gm >> rs_shift) * rs_mul + rs_off];
                    v0 *= rs; v1 *= rs;
                }
                long long off = (long long)gm * ldc + cb;
                if (OC) {
                    *reinterpret_cast<__half2*>(&Ch[off]) = __floats2half2_rn(v0, v1);
                } else {
                    if (beta != 0.f) {
                        float2 c = *reinterpret_cast<float2*>(&Cf[off]);
                        v0 += beta * c.x; v1 += beta * c.y;
                    }
                    *reinterpret_cast<float2*>(&Cf[off]) = make_float2(v0, v1);
                }
            }
        }
    }
}

// ---------------------------------------------------------------------------
// Conversions
// ---------------------------------------------------------------------------
__global__ void f2h_copy_k(const float* __restrict__ src, __half* __restrict__ dst, long long n4)
{
    long long i = (long long)blockIdx.x * blockDim.x + threadIdx.x;
    if (i >= n4) return;
    float4 v = reinterpret_cast<const float4*>(src)[i];
    __half2 a = __floats2half2_rn(v.x, v.y);
    __half2 b = __floats2half2_rn(v.z, v.w);
    reinterpret_cast<__half2*>(dst)[2*i]   = a;
    reinterpret_cast<__half2*>(dst)[2*i+1] = b;
}

// src fp32 [R,C] -> dst fp16 [C,R], batched
__global__ void transpose_f2h_k(const float* __restrict__ src, __half* __restrict__ dst,
                                int R, int C, long long bs)
{
    __shared__ float t[32][33];
    src += (long long)blockIdx.z * bs;
    dst += (long long)blockIdx.z * bs;
    int r0 = blockIdx.y * 32, c0 = blockIdx.x * 32;
    int tx = threadIdx.x, ty = threadIdx.y;
#pragma unroll
    for (int i = 0; i < 32; i += 8) {
        int rr = r0 + ty + i, cc = c0 + tx;
        t[ty + i][tx] = (rr < R && cc < C) ? src[(long long)rr * C + cc] : 0.f;
    }
    __syncthreads();
#pragma unroll
    for (int i = 0; i < 32; i += 8) {
        int cc = c0 + ty + i, rr = r0 + tx;
        if (cc < C && rr < R) dst[(long long)cc * R + rr] = __float2half_rn(t[tx][ty + i]);
    }
}

// src fp16 [R,C] -> dst fp16 [C,R], batched
__global__ void transpose_h_k(const __half* __restrict__ src, __half* __restrict__ dst,
                              int R, int C, long long bs)
{
    __shared__ __half t[32][33];
    src += (long long)blockIdx.z * bs;
    dst += (long long)blockIdx.z * bs;
    int r0 = blockIdx.y * 32, c0 = blockIdx.x * 32;
    int tx = threadIdx.x, ty = threadIdx.y;
#pragma unroll
    for (int i = 0; i < 32; i += 8) {
        int rr = r0 + ty + i, cc = c0 + tx;
        t[ty + i][tx] = (rr < R && cc < C) ? src[(long long)rr * C + cc] : __half(0.f);
    }
    __syncthreads();
#pragma unroll
    for (int i = 0; i < 32; i += 8) {
        int cc = c0 + ty + i, rr = r0 + tx;
        if (cc < C && rr < R) dst[(long long)cc * R + rr] = t[tx][ty + i];
    }
}

// ---------------------------------------------------------------------------
// Router / norm / softmax / elementwise
// ---------------------------------------------------------------------------
__global__ void rowrms_k(const float* __restrict__ X, float* __restrict__ rrms, int ncols)
{
    int row = blockIdx.x;
    const float* p = X + (long long)row * ncols;
    __shared__ float red[256];
    float s = 0.f;
    for (int c = threadIdx.x; c < ncols; c += 256) { float v = p[c]; s += v * v; }
    red[threadIdx.x] = s; __syncthreads();
    for (int st = 128; st > 0; st >>= 1) {
        if (threadIdx.x < st) red[threadIdx.x] += red[threadIdx.x + st];
        __syncthreads();
    }
    if (threadIdx.x == 0) rrms[row] = rsqrtf(red[0] / ncols + 1e-6f);
}

__global__ void xbar_k(const float* __restrict__ X, const float* __restrict__ rrms,
                       const float* __restrict__ w, float* __restrict__ xbar)
{
    int idx = blockIdx.x * blockDim.x + threadIdx.x;
    if (idx >= BB * DD) return;
    int b = idx / DD, d = idx % DD;
    const float* xp = X + (long long)b * NQL * DD + d;
    const float* rp = rrms + b * NQL;
    float s = 0.f;
    for (int n = 0; n < NQL; n++) s += xp[(long long)n * DD] * rp[n];
    xbar[idx] = w[d] * s * (1.f / NQL);
}

__global__ void router_logits_k(const float* __restrict__ xbar, const float* __restrict__ W,
                                const float* __restrict__ bias, float* __restrict__ logits)
{
    int b = blockIdx.x >> 2, e = blockIdx.x & 3;
    __shared__ float red[256];
    float s = 0.f;
    for (int k = threadIdx.x; k < DD; k += 256) s += xbar[b * DD + k] * W[k * 4 + e];
    red[threadIdx.x] = s; __syncthreads();
    for (int st = 128; st > 0; st >>= 1) {
        if (threadIdx.x < st) red[threadIdx.x] += red[threadIdx.x + st];
        __syncthreads();
    }
    if (threadIdx.x == 0) logits[b * 4 + e] = red[0] + bias[e];
}

__global__ void gate_k(const float* __restrict__ logits, float* __restrict__ gate)
{
    int b = threadIdx.x;
    if (b >= BB) return;
    float l[4]; float mx = -1e30f;
    for (int e = 0; e < 4; e++) { l[e] = logits[b * 4 + e]; mx = fmaxf(mx, l[e]); }
    float s = 0.f;
    for (int e = 0; e < 4; e++) { l[e] = expf(l[e] - mx); s += l[e]; }
    for (int e = 0; e < 4; e++) l[e] /= s;
    int i1 = 0;
    for (int e = 1; e < 4; e++) if (l[e] > l[i1]) i1 = e;
    int i2 = -1;
    for (int e = 0; e < 4; e++) if (e != i1 && (i2 < 0 || l[e] > l[i2])) i2 = e;
    float denom = l[i1] + l[i2] + 1e-10f;
    float g[4] = {0.f, 0.f, 0.f, 0.f};
    g[i1] = l[i1] / denom;
    g[i2] = l[i2] / denom;
    for (int e = 0; e < 4; e++) gate[b * 4 + e] = g[e];
}

// in-place softmax over fp16 scores (fp32 math in smem)
__global__ void softmax_hh_k(__half* __restrict__ P, int ncols)
{
    int row = blockIdx.x;
    __half* p = P + (long long)row * ncols;
    __shared__ float sm[1024];
    __shared__ float red[256];
    int tid = threadIdx.x;
    float mx = -1e30f;
    for (int c = tid; c < ncols; c += 256) { float v = __half2float(p[c]); sm[c] = v; mx = fmaxf(mx, v); }
    red[tid] = mx; __syncthreads();
    for (int st = 128; st > 0; st >>= 1) {
        if (tid < st) red[tid] = fmaxf(red[tid], red[tid + st]);
        __syncthreads();
    }
    mx = red[0]; __syncthreads();
    float sum = 0.f;
    for (int c = tid; c < ncols; c += 256) { float e = __expf(sm[c] - mx); sm[c] = e; sum += e; }
    red[tid] = sum; __syncthreads();
    for (int st = 128; st > 0; st >>= 1) {
        if (tid < st) red[tid] += red[tid + st];
        __syncthreads();
    }
    float inv = 1.f / red[0];
    __syncthreads();
    for (int c = tid; c < ncols; c += 256) p[c] = __float2half_rn(sm[c] * inv);
}

__global__ void x1_k(const float* __restrict__ xq, const float* __restrict__ delta,
                     const float* __restrict__ alpha1, float* __restrict__ x1)
{
    int idx = blockIdx.x * blockDim.x + threadIdx.x;
    if (idx >= MQ * DD) return;
    float s = 1.f / (1.f + expf(-alpha1[0]));
    x1[idx] = xq[idx] + s * delta[idx];
}

__global__ void rmsnorm_h_k(const float* __restrict__ X, const float* __restrict__ w,
                            __half* __restrict__ Y, int ncols)
{
    int row = blockIdx.x;
    const float* p = X + (long long)row * ncols;
    __half* q = Y + (long long)row * ncols;
    __shared__ float red[256];
    float s = 0.f;
    for (int c = threadIdx.x; c < ncols; c += 256) { float v = p[c]; s += v * v; }
    red[threadIdx.x] = s; __syncthreads();
    for (int st = 128; st > 0; st >>= 1) {
        if (threadIdx.x < st) red[threadIdx.x] += red[threadIdx.x + st];
        __syncthreads();
    }
    float scale = rsqrtf(red[0] / ncols + 1e-6f);
    __syncthreads();
    for (int c = threadIdx.x; c < ncols; c += 256) q[c] = __float2half_rn(w[c] * p[c] * scale);
}

__global__ void silu_add_h_k(const float* __restrict__ G, const float* __restrict__ U,
                             __half* __restrict__ Xd, long long n)
{
    long long idx = (long long)blockIdx.x * blockDim.x + threadIdx.x;
    if (idx >= n) return;
    float g = G[idx];
    Xd[idx] = __float2half_rn(g / (1.f + expf(-g)) + U[idx]);
}

__global__ void out_k(const float* __restrict__ x1, const float* __restrict__ T,
                      const float* __restrict__ alpha2, float* __restrict__ out)
{
    int idx = blockIdx.x * blockDim.x + threadIdx.x;
    if (idx >= MQ * DD) return;
    float s = 1.f / (1.f + expf(-alpha2[0]));
    out[idx] = x1[idx] + s * T[idx];
}

// ---------------------------------------------------------------------------
// Host helpers
// ---------------------------------------------------------------------------
static void hgemm(int OC, int M, int N, int K,
                  const __half* A, int lda, long long sA1, long long sA2,
                  const __half* B, int ldb, long long sB1, long long sB2,
                  void* C, int ldc, long long sC1, long long sC2,
                  int Z, int zdiv, float alpha, float beta, const float* bias,
                  const float* rowscale = nullptr, int rs_shift = 0, int rs_mul = 0, int rs_off = 0)
{
    dim3 grid((N + 127) / 128, (M + 127) / 128, Z);
    if (OC)
        hgemm_k<1><<<grid, NT, HG_SMEM>>>(M, N, K, A, lda, sA1, sA2, B, ldb, sB1, sB2,
                                          C, ldc, sC1, sC2, zdiv, alpha, beta, bias,
                                          rowscale, rs_shift, rs_mul, rs_off);
    else
        hgemm_k<0><<<grid, NT, HG_SMEM>>>(M, N, K, A, lda, sA1, sA2, B, ldb, sB1, sB2,
                                          C, ldc, sC1, sC2, zdiv, alpha, beta, bias,
                                          rowscale, rs_shift, rs_mul, rs_off);
}

template <typename T>
static T* sym(const void* s)
{
    void* p = nullptr;
    cudaGetSymbolAddress(&p, (const void*)s);
    return (T*)p;
}

static void f2h_copy(const float* src, __half* dst, long long n)
{
    long long n4 = n / 4;
    f2h_copy_k<<<(int)((n4 + 255) / 256), 256>>>(src, dst, n4);
}

static void transpose_f2h(const float* src, __half* dst, int R, int C, int batch)
{
    dim3 grid((C + 31) / 32, (R + 31) / 32, batch);
    transpose_f2h_k<<<grid, dim3(32, 8)>>>(src, dst, R, C, (long long)R * C);
}

static void transpose_h(const __half* src, __half* dst, int R, int C, int batch)
{
    dim3 grid((C + 31) / 32, (R + 31) / 32, batch);
    transpose_h_k<<<grid, dim3(32, 8)>>>(src, dst, R, C, (long long)R * C);
}

// ---------------------------------------------------------------------------
// kernel_launch
// ---------------------------------------------------------------------------
extern "C" void kernel_launch(void* const* d_in, const int* in_sizes, int n_in,
                              void* d_out, int out_size)
{
    const float* x_q      = (const float*)d_in[0];
    const float* z_a      = (const float*)d_in[1];
    const float* z_v      = (const float*)d_in[2];
    const float* z_av     = (const float*)d_in[3];
    const float* ln1_w    = (const float*)d_in[4];
    const float* router_W = (const float*)d_in[5];
    const float* router_b = (const float*)d_in[6];
    const float* Wq       = (const float*)d_in[7];
    const float* bq       = (const float*)d_in[8];
    const float* Wk       = (const float*)d_in[9];
    const float* bk       = (const float*)d_in[10];
    const float* Wv       = (const float*)d_in[11];
    const float* bv       = (const float*)d_in[12];
    const float* Wo       = (const float*)d_in[13];
    const float* bo       = (const float*)d_in[14];
    const float* alpha1   = (const float*)d_in[15];
    const float* alpha2   = (const float*)d_in[16];
    const float* ln2_w    = (const float*)d_in[17];
    const float* gate_w   = (const float*)d_in[18];
    const float* up_w     = (const float*)d_in[19];
    const float* down_w   = (const float*)d_in[20];
    const float* la_gA    = (const float*)d_in[21];
    const float* la_gB    = (const float*)d_in[22];
    const float* la_uA    = (const float*)d_in[23];
    const float* la_uB    = (const float*)d_in[24];
    const float* la_dA    = (const float*)d_in[25];
    const float* la_dB    = (const float*)d_in[26];
    float* out = (float*)d_out;

    cudaFuncSetAttribute(hgemm_k<0>, cudaFuncAttributeMaxDynamicSharedMemorySize, HG_SMEM);
    cudaFuncSetAttribute(hgemm_k<1>, cudaFuncAttributeMaxDynamicSharedMemorySize, HG_SMEM);

    float* pRrms  = sym<float>(&g_rrms);
    float* pXbar  = sym<float>(&g_xbar);
    float* pLog   = sym<float>(&g_logits);
    float* pGate  = sym<float>(&g_gate);
    float* pDelta = sym<float>(&g_delta);
    float* pX1    = sym<float>(&g_x1);
    float* pG     = sym<float>(&g_G);
    float* pU     = sym<float>(&g_U);
    float* pT     = sym<float>(&g_T);
    __half* hZ   = sym<__half>(&g_hZ);
    __half* hW   = sym<__half>(&g_hW);
    __half* hM   = sym<__half>(&g_hM);
    __half* hLa  = sym<__half>(&g_hLa);
    __half* hQ   = sym<__half>(&g_hQ);
    __half* hK   = sym<__half>(&g_hK);
    __half* hV   = sym<__half>(&g_hV);
    __half* hVt  = sym<__half>(&g_hVt);
    __half* hO   = sym<__half>(&g_hO);
    __half* hH   = sym<__half>(&g_hH);
    __half* hP   = sym<__half>(&g_hP);
    __half* hXd  = sym<__half>(&g_hXd);
    __half* hLt  = sym<__half>(&g_hLt);

    const long long WSZ = (long long)3 * DD * DD;
    __half* tWqT = hW;            __half* tWkT = hW + WSZ;
    __half* tWvT = hW + 2 * WSZ;  __half* tWoT = hW + 3 * WSZ;
    const long long MSZ = (long long)DD * FFD;
    __half* tGwT = hM; __half* tUwT = hM + MSZ; __half* tDwT = hM + 2 * MSZ;
    const long long ZA = (long long)BB * 512 * DD;
    const long long ZAV = (long long)BB * 1024 * DD;
    __half* hZa  = hZ;
    __half* hZv  = hZ + ZA;
    __half* hZav = hZ + 2 * ZA;
    __half* hXq  = hZ + 2 * ZA + ZAV;
    __half* tgA = hLa;             __half* tgB = tgA + DD * RR;
    __half* tuA = tgB + RR * FFD;  __half* tuB = tuA + DD * RR;
    __half* tdA = tuB + RR * FFD;  __half* tdB = tdA + FFD * RR;

    // ---- operand conversions ----
    transpose_f2h(Wq, tWqT, DD, DD, 3);
    transpose_f2h(Wk, tWkT, DD, DD, 3);
    transpose_f2h(Wv, tWvT, DD, DD, 3);
    transpose_f2h(Wo, tWoT, DD, DD, 3);
    transpose_f2h(gate_w, tGwT, DD, FFD, 1);
    transpose_f2h(up_w,   tUwT, DD, FFD, 1);
    transpose_f2h(down_w, tDwT, FFD, DD, 1);
    transpose_f2h(la_gA, tgA, DD, RR, 1);
    transpose_f2h(la_gB, tgB, RR, FFD, 1);
    transpose_f2h(la_uA, tuA, DD, RR, 1);
    transpose_f2h(la_uB, tuB, RR, FFD, 1);
    transpose_f2h(la_dA, tdA, FFD, RR, 1);
    transpose_f2h(la_dB, tdB, RR, DD, 1);
    f2h_copy(z_a,  hZa,  ZA);
    f2h_copy(z_v,  hZv,  ZA);
    f2h_copy(z_av, hZav, ZAV);
    f2h_copy(x_q,  hXq,  ZAV);

    const int EW_B = (MQ * DD + 255) / 256;

    // ---- router (fp32 path on original inputs) ----
    rowrms_k<<<MQ, 256>>>(x_q, pRrms, DD);
    xbar_k<<<(BB * DD + 255) / 256, 256>>>(x_q, pRrms, ln1_w, pXbar);
    router_logits_k<<<BB * 4, 256>>>(pXbar, router_W, router_b, pLog);
    gate_k<<<1, 32>>>(pLog, pGate);

    // ---- experts ----
    const __half* hzs[3] = {hZa, hZv, hZav};
    const int     nks[3] = {512, 512, 1024};
    const float att_scale = 0.08838834764831843f;  // 1/sqrt(128)

    for (int e = 0; e < 3; e++) {
        const __half* hz = hzs[e];
        int NK = nks[e];
        int MZ = BB * NK;

        hgemm(1, MQ, DD, DD, hXq, DD, 0, 0, tWqT + (long long)e * DD * DD, DD, 0, 0,
              hQ, DD, 0, 0, 1, 1, 1.f, 0.f, bq + e * DD);
        hgemm(1, MZ, DD, DD, hz, DD, 0, 0, tWkT + (long long)e * DD * DD, DD, 0, 0,
              hK, DD, 0, 0, 1, 1, 1.f, 0.f, bk + e * DD);
        hgemm(1, MZ, DD, DD, hz, DD, 0, 0, tWvT + (long long)e * DD * DD, DD, 0, 0,
              hV, DD, 0, 0, 1, 1, 1.f, 0.f, bv + e * DD);

        transpose_h(hV, hVt, NK, DD, BB);

        // scores -> fp16 in hP (alpha folds 1/sqrt(dh))
        hgemm(1, NQL, NK, DHH,
              hQ, DD, (long long)NQL * DD, DHH,
              hK, DD, (long long)NK * DD, DHH,
              hP, NK, (long long)HH * NQL * NK, (long long)NQL * NK,
              BB * HH, HH, att_scale, 0.f, nullptr);

        softmax_hh_k<<<BB * HH * NQL, 256>>>(hP, NK);

        hgemm(1, NQL, DHH, NK,
              hP, NK, (long long)HH * NQL * NK, (long long)NQL * NK,
              hVt, NK, (long long)DD * NK, (long long)DHH * NK,
              hO, DD, (long long)NQL * DD, DHH,
              BB * HH, HH, 1.f, 0.f, nullptr);

        hgemm(0, MQ, DD, DD, hO, DD, 0, 0, tWoT + (long long)e * DD * DD, DD, 0, 0,
              pDelta, DD, 0, 0, 1, 1, 1.f, (e == 0) ? 0.f : 1.f, bo + e * DD,
              pGate, 10, 4, e);
    }

    // ---- x1 = x_q + sigmoid(alpha1)*delta ----
    x1_k<<<EW_B, 256>>>(x_q, pDelta, alpha1, pX1);

    // ---- MLP with LoRA ----
    rmsnorm_h_k<<<MQ, 256>>>(pX1, ln2_w, hH, DD);

    // gate path
    hgemm(0, MQ, FFD, DD, hH, DD, 0, 0, tGwT, DD, 0, 0, pG, FFD, 0, 0, 1, 1, 1.f, 0.f, nullptr);
    hgemm(1, MQ, RR, DD, hH, DD, 0, 0, tgA, DD, 0, 0, hLt, RR, 0, 0, 1, 1, 1.f, 0.f, nullptr);
    hgemm(0, MQ, FFD, RR, hLt, RR, 0, 0, tgB, RR, 0, 0, pG, FFD, 0, 0, 1, 1, LORA_SCALE, 1.f, nullptr);

    // up path
    hgemm(0, MQ, FFD, DD, hH, DD, 0, 0, tUwT, DD, 0, 0, pU, FFD, 0, 0, 1, 1, 1.f, 0.f, nullptr);
    hgemm(1, MQ, RR, DD, hH, DD, 0, 0, tuA, DD, 0, 0, hLt, RR, 0, 0, 1, 1, 1.f, 0.f, nullptr);
    hgemm(0, MQ, FFD, RR, hLt, RR, 0, 0, tuB, RR, 0, 0, pU, FFD, 0, 0, 1, 1, LORA_SCALE, 1.f, nullptr);

    // x_down = silu(gate) + up -> fp16
    {
        long long n = (long long)MQ * FFD;
        silu_add_h_k<<<(int)((n + 255) / 256), 256>>>(pG, pU, hXd, n);
    }

    // down path
    hgemm(0, MQ, DD, FFD, hXd, FFD, 0, 0, tDwT, FFD, 0, 0, pT, DD, 0, 0, 1, 1, 1.f, 0.f, nullptr);
    hgemm(1, MQ, RR, FFD, hXd, FFD, 0, 0, tdA, FFD, 0, 0, hLt, RR, 0, 0, 1, 1, 1.f, 0.f, nullptr);
    hgemm(0, MQ, DD, RR, hLt, RR, 0, 0, tdB, RR, 0, 0, pT, DD, 0, 0, 1, 1, LORA_SCALE, 1.f, nullptr);

    // out = x1 + sigmoid(alpha2)*mlp_out
    out_k<<<EW_B, 256>>>(pX1, pT, alpha2, out);
}

// round 17
// speedup vs baseline: 1.4712x; 1.2549x over previous
#include <cuda_runtime.h>
#include <cuda_fp16.h>
#include <math.h>
#include <stdint.h>

// ---------------------------------------------------------------------------
// Problem constants
// ---------------------------------------------------------------------------
#define BB   8
#define NQL  1024
#define DD   2048
#define HH   16
#define DHH  128
#define FFD  8192
#define RR   16
#define MQ   (BB*NQL)
#define LORA_SCALE 1.0f

// ---------------------------------------------------------------------------
// Scratch (device globals)
// ---------------------------------------------------------------------------
__device__ __align__(256) float g_rrms[MQ];
__device__ __align__(256) float g_xbar[BB*DD];
__device__ __align__(256) float g_logits[BB*4];
__device__ __align__(256) float g_gate[BB*4];
__device__ __align__(256) float g_delta[(long long)MQ*DD];
__device__ __align__(256) float g_x1[(long long)MQ*DD];
__device__ __align__(256) float g_G[(long long)MQ*FFD];
__device__ __align__(256) float g_U[(long long)MQ*FFD];
__device__ __align__(256) float g_T[(long long)MQ*DD];
// fp16 operand buffers
__device__ __align__(256) __half g_hZ[(long long)50331648];       // z_a,z_v,z_av,x_q
__device__ __align__(256) __half g_hW[(long long)4*3*DD*DD];      // WqT,WkT,WvT,WoT
__device__ __align__(256) __half g_hM[(long long)3*DD*FFD];       // gateT,upT,downT
__device__ __align__(256) __half g_hLa[491520];                   // LoRA transposed
__device__ __align__(256) __half g_hQ[(long long)MQ*DD];
__device__ __align__(256) __half g_hK[(long long)MQ*DD];
__device__ __align__(256) __half g_hV[(long long)MQ*DD];
__device__ __align__(256) __half g_hVt[(long long)MQ*DD];
__device__ __align__(256) __half g_hO[(long long)MQ*DD];
__device__ __align__(256) __half g_hH[(long long)MQ*DD];
__device__ __align__(256) __half g_hP[(long long)BB*HH*NQL*1024]; // fp16 scores/probs (in-place)
__device__ __align__(256) __half g_hXd[(long long)MQ*FFD];
__device__ __align__(256) __half g_hLt[(long long)MQ*RR];

// ---------------------------------------------------------------------------
// Helpers
// ---------------------------------------------------------------------------
__device__ __forceinline__ void mma_f16(float& c0, float& c1, float& c2, float& c3,
                                        unsigned a0, unsigned a1, unsigned a2, unsigned a3,
                                        unsigned b0, unsigned b1)
{
    asm volatile(
        "mma.sync.aligned.m16n8k16.row.col.f32.f16.f16.f32 "
        "{%0,%1,%2,%3}, {%4,%5,%6,%7}, {%8,%9}, {%0,%1,%2,%3};"
        : "+f"(c0), "+f"(c1), "+f"(c2), "+f"(c3)
        : "r"(a0), "r"(a1), "r"(a2), "r"(a3), "r"(b0), "r"(b1));
}

__device__ __forceinline__ void ldsm4(unsigned& r0, unsigned& r1, unsigned& r2, unsigned& r3,
                                      unsigned addr)
{
    asm volatile("ldmatrix.sync.aligned.m8n8.x4.shared.b16 {%0,%1,%2,%3}, [%4];"
                 : "=r"(r0), "=r"(r1), "=r"(r2), "=r"(r3) : "r"(addr));
}

__device__ __forceinline__ void cp16(void* dst_smem, const void* src, bool pred)
{
    unsigned d = (unsigned)__cvta_generic_to_shared(dst_smem);
    int sz = pred ? 16 : 0;
    asm volatile("cp.async.cg.shared.global [%0], [%1], 16, %2;\n"
                 :: "r"(d), "l"(src), "r"(sz));
}
__device__ __forceinline__ void cp_commit() { asm volatile("cp.async.commit_group;\n"); }
template <int N>
__device__ __forceinline__ void cp_wait() { asm volatile("cp.async.wait_group %0;\n" :: "n"(N)); }

// ---------------------------------------------------------------------------
// fp16 tensor-core strided-batched GEMM, fp32 accumulate, ldmatrix frags.
// A [M,K] row-major fp16 (lda). B [N,K] row-major fp16 (ldb) -> used as B^T.
// C = rowscale * (alpha * A@B^T + bias) + beta*C ; OC=1 -> fp16 C, OC=0 -> fp32 C.
// Block 128x128x32, 3-stage cp.async (one barrier per k-iter); 4 warps, 64x64.
// Requires N even.
// Expert-skip: if skipg != nullptr, batch b = (smode>0 ? bm/smode : z/(-smode));
// inactive (skipg[b*4+eoff]==0) CTAs: return if no rowscale, else acc stays 0.
// ---------------------------------------------------------------------------
#define NT 128
#define AST 40                       // halfs per row (32 + 8 pad): 80B rows
#define STG (128*AST)                // 5120 halfs per stage per operand
#define HG_SMEM (6*STG*2)            // 3 stages x (A+B) = 61440 B dynamic

template <int OC>
__global__ __launch_bounds__(NT, 2)
void hgemm_k(int M, int N, int K,
             const __half* __restrict__ A, int lda, long long sA1, long long sA2,
             const __half* __restrict__ B, int ldb, long long sB1, long long sB2,
             void* __restrict__ Cv, int ldc, long long sC1, long long sC2,
             int zdiv, float alpha, float beta, const float* __restrict__ bias,
             const float* __restrict__ rowscale, int rs_shift, int rs_mul, int rs_off,
             const float* __restrict__ skipg, int smode, int eoff)
{
    extern __shared__ __half sm[];               // [3 stages][A:STG | B:STG]
    __half* As = sm;
    __half* Bs = sm + STG;

    int z = blockIdx.z;
    int bm = blockIdx.y * 128;
    int bn = blockIdx.x * 128;

    bool active = true;
    if (skipg) {
        int b = (smode > 0) ? (bm / smode) : (z / (-smode));
        active = (skipg[b * 4 + eoff] != 0.f);
        if (!active && rowscale == nullptr) return;
    }

    A += (long long)(z / zdiv) * sA1 + (long long)(z % zdiv) * sA2;
    B += (long long)(z / zdiv) * sB1 + (long long)(z % zdiv) * sB2;
    float* Cf = (float*)Cv + ((long long)(z / zdiv) * sC1 + (long long)(z % zdiv) * sC2);
    __half* Ch = (__half*)Cv + ((long long)(z / zdiv) * sC1 + (long long)(z % zdiv) * sC2);

    int tid  = threadIdx.x;
    int lane = tid & 31;
    int wid  = tid >> 5;
    int wm = (wid & 1) * 64;
    int wn = (wid >> 1) * 64;

    float acc[4][8][4];
#pragma unroll
    for (int i = 0; i < 4; i++)
#pragma unroll
        for (int j = 0; j < 8; j++)
#pragma unroll
            for (int q = 0; q < 4; q++) acc[i][j][q] = 0.f;

    int ktiles = (K + 31) >> 5;

    auto load_tile = [&](int kt, int stage) {
        int k0 = kt * 32;
        __half* Ad = As + stage * 2 * STG;
        __half* Bd = Bs + stage * 2 * STG;
#pragma unroll
        for (int i = 0; i < 4; i++) {
            int idx = tid + i * NT;        // 0..511
            int row = idx >> 2;
            int c   = idx & 3;
            int gk  = k0 + c * 8;
            {
                int gm = bm + row;
                cp16(&Ad[row*AST + c*8],
                     A + (long long)gm * lda + gk, (gm < M) && (gk < K));
            }
            {
                int gn = bn + row;
                cp16(&Bd[row*AST + c*8],
                     B + (long long)gn * ldb + gk, (gn < N) && (gk < K));
            }
        }
        cp_commit();
    };

    if (active) {
        load_tile(0, 0);
        if (ktiles > 1) load_tile(1, 1);

        // precomputed ldmatrix lane-address components (in halfs)
        int a_row = wm + (lane & 15);          // + mi*16
        int a_col = (lane >> 4) * 8;           // + kk
        int b_row = wn + ((lane >> 4) * 8) + (lane & 7);   // + p*16
        int b_col = ((lane >> 3) & 1) * 8;     // + kk

        int stage = 0;
        for (int kt = 0; kt < ktiles; kt++) {
            if (kt + 1 < ktiles) cp_wait<1>(); else cp_wait<0>();
            __syncthreads();

            unsigned abase = (unsigned)__cvta_generic_to_shared(As + stage * 2 * STG);
            unsigned bbase = (unsigned)__cvta_generic_to_shared(Bs + stage * 2 * STG);

#pragma unroll
            for (int ks = 0; ks < 2; ks++) {
                int kk = ks * 16;
                unsigned afr[4][4];
#pragma unroll
                for (int mi = 0; mi < 4; mi++) {
                    unsigned addr = abase + (unsigned)(((a_row + mi * 16) * AST + kk + a_col) * 2);
                    ldsm4(afr[mi][0], afr[mi][1], afr[mi][2], afr[mi][3], addr);
                }
                unsigned bfr[8][2];
#pragma unroll
                for (int p = 0; p < 4; p++) {
                    unsigned addr = bbase + (unsigned)(((b_row + p * 16) * AST + kk + b_col) * 2);
                    ldsm4(bfr[2*p][0], bfr[2*p][1], bfr[2*p+1][0], bfr[2*p+1][1], addr);
                }
#pragma unroll
                for (int mi = 0; mi < 4; mi++)
#pragma unroll
                    for (int ni = 0; ni < 8; ni++)
                        mma_f16(acc[mi][ni][0], acc[mi][ni][1], acc[mi][ni][2], acc[mi][ni][3],
                                afr[mi][0], afr[mi][1], afr[mi][2], afr[mi][3],
                                bfr[ni][0], bfr[ni][1]);
            }

            if (kt + 2 < ktiles) {
                int st2 = stage + 2; if (st2 >= 3) st2 -= 3;
                load_tile(kt + 2, st2);
            }
            if (++stage == 3) stage = 0;
        }
    }

    // ---- epilogue (paired stores; N even) ----
    // inactive+rowscale: acc=0 and rowscale=0 -> writes exact 0 (beta=0) or beta*C.
#pragma unroll
    for (int mi = 0; mi < 4; mi++) {
        int r0 = bm + wm + mi * 16 + (lane >> 2);
#pragma unroll
        for (int ni = 0; ni < 8; ni++) {
            int cb = bn + wn + ni * 8 + 2 * (lane & 3);
            if (cb >= N) continue;
            float b0 = bias ? bias[cb] : 0.f;
            float b1 = bias ? bias[cb + 1] : 0.f;
#pragma unroll
            for (int h = 0; h < 2; h++) {
                int gm = r0 + h * 8;
                if (gm >= M) continue;
                float v0 = alpha * acc[mi][ni][2*h]     + b0;
                float v1 = alpha * acc[mi][ni][2*h + 1] + b1;
                if (rowscale) {
                    float rs = rowscale[(gm >> rs_shift) * rs_mul + rs_off];
                    v0 *= rs; v1 *= rs;
                }
                long long off = (long long)gm * ldc + cb;
                if (OC) {
                    *reinterpret_cast<__half2*>(&Ch[off]) = __floats2half2_rn(v0, v1);
                } else {
                    if (beta != 0.f) {
                        float2 c = *reinterpret_cast<float2*>(&Cf[off]);
                        v0 += beta * c.x; v1 += beta * c.y;
                    }
                    *reinterpret_cast<float2*>(&Cf[off]) = make_float2(v0, v1);
                }
            }
        }
    }
}

// ---------------------------------------------------------------------------
// Conversions
// ---------------------------------------------------------------------------
__global__ void f2h_copy_k(const float* __restrict__ src, __half* __restrict__ dst, long long n4)
{
    long long i = (long long)blockIdx.x * blockDim.x + threadIdx.x;
    if (i >= n4) return;
    float4 v = reinterpret_cast<const float4*>(src)[i];
    __half2 a = __floats2half2_rn(v.x, v.y);
    __half2 b = __floats2half2_rn(v.z, v.w);
    reinterpret_cast<__half2*>(dst)[2*i]   = a;
    reinterpret_cast<__half2*>(dst)[2*i+1] = b;
}

// src fp32 [R,C] -> dst fp16 [C,R], batched
__global__ void transpose_f2h_k(const float* __restrict__ src, __half* __restrict__ dst,
                                int R, int C, long long bs)
{
    __shared__ float t[32][33];
    src += (long long)blockIdx.z * bs;
    dst += (long long)blockIdx.z * bs;
    int r0 = blockIdx.y * 32, c0 = blockIdx.x * 32;
    int tx = threadIdx.x, ty = threadIdx.y;
#pragma unroll
    for (int i = 0; i < 32; i += 8) {
        int rr = r0 + ty + i, cc = c0 + tx;
        t[ty + i][tx] = (rr < R && cc < C) ? src[(long long)rr * C + cc] : 0.f;
    }
    __syncthreads();
#pragma unroll
    for (int i = 0; i < 32; i += 8) {
        int cc = c0 + ty + i, rr = r0 + tx;
        if (cc < C && rr < R) dst[(long long)cc * R + rr] = __float2half_rn(t[tx][ty + i]);
    }
}

// src fp16 [R,C] -> dst fp16 [C,R], batched; optional per-batch expert skip
__global__ void transpose_h_k(const __half* __restrict__ src, __half* __restrict__ dst,
                              int R, int C, long long bs,
                              const float* __restrict__ skipg, int eoff)
{
    if (skipg && skipg[blockIdx.z * 4 + eoff] == 0.f) return;
    __shared__ __half t[32][33];
    src += (long long)blockIdx.z * bs;
    dst += (long long)blockIdx.z * bs;
    int r0 = blockIdx.y * 32, c0 = blockIdx.x * 32;
    int tx = threadIdx.x, ty = threadIdx.y;
#pragma unroll
    for (int i = 0; i < 32; i += 8) {
        int rr = r0 + ty + i, cc = c0 + tx;
        t[ty + i][tx] = (rr < R && cc < C) ? src[(long long)rr * C + cc] : __half(0.f);
    }
    __syncthreads();
#pragma unroll
    for (int i = 0; i < 32; i += 8) {
        int cc = c0 + ty + i, rr = r0 + tx;
        if (cc < C && rr < R) dst[(long long)cc * R + rr] = t[tx][ty + i];
    }
}

// ---------------------------------------------------------------------------
// Router / norm / softmax / elementwise
// ---------------------------------------------------------------------------
__global__ void rowrms_k(const float* __restrict__ X, float* __restrict__ rrms, int ncols)
{
    int row = blockIdx.x;
    const float* p = X + (long long)row * ncols;
    __shared__ float red[256];
    float s = 0.f;
    for (int c = threadIdx.x; c < ncols; c += 256) { float v = p[c]; s += v * v; }
    red[threadIdx.x] = s; __syncthreads();
    for (int st = 128; st > 0; st >>= 1) {
        if (threadIdx.x < st) red[threadIdx.x] += red[threadIdx.x + st];
        __syncthreads();
    }
    if (threadIdx.x == 0) rrms[row] = rsqrtf(red[0] / ncols + 1e-6f);
}

__global__ void xbar_k(const float* __restrict__ X, const float* __restrict__ rrms,
                       const float* __restrict__ w, float* __restrict__ xbar)
{
    int idx = blockIdx.x * blockDim.x + threadIdx.x;
    if (idx >= BB * DD) return;
    int b = idx / DD, d = idx % DD;
    const float* xp = X + (long long)b * NQL * DD + d;
    const float* rp = rrms + b * NQL;
    float s = 0.f;
    for (int n = 0; n < NQL; n++) s += xp[(long long)n * DD] * rp[n];
    xbar[idx] = w[d] * s * (1.f / NQL);
}

__global__ void router_logits_k(const float* __restrict__ xbar, const float* __restrict__ W,
                                const float* __restrict__ bias, float* __restrict__ logits)
{
    int b = blockIdx.x >> 2, e = blockIdx.x & 3;
    __shared__ float red[256];
    float s = 0.f;
    for (int k = threadIdx.x; k < DD; k += 256) s += xbar[b * DD + k] * W[k * 4 + e];
    red[threadIdx.x] = s; __syncthreads();
    for (int st = 128; st > 0; st >>= 1) {
        if (threadIdx.x < st) red[threadIdx.x] += red[threadIdx.x + st];
        __syncthreads();
    }
    if (threadIdx.x == 0) logits[b * 4 + e] = red[0] + bias[e];
}

__global__ void gate_k(const float* __restrict__ logits, float* __restrict__ gate)
{
    int b = threadIdx.x;
    if (b >= BB) return;
    float l[4]; float mx = -1e30f;
    for (int e = 0; e < 4; e++) { l[e] = logits[b * 4 + e]; mx = fmaxf(mx, l[e]); }
    float s = 0.f;
    for (int e = 0; e < 4; e++) { l[e] = expf(l[e] - mx); s += l[e]; }
    for (int e = 0; e < 4; e++) l[e] /= s;
    int i1 = 0;
    for (int e = 1; e < 4; e++) if (l[e] > l[i1]) i1 = e;
    int i2 = -1;
    for (int e = 0; e < 4; e++) if (e != i1 && (i2 < 0 || l[e] > l[i2])) i2 = e;
    float denom = l[i1] + l[i2] + 1e-10f;
    float g[4] = {0.f, 0.f, 0.f, 0.f};
    g[i1] = l[i1] / denom;
    g[i2] = l[i2] / denom;
    for (int e = 0; e < 4; e++) gate[b * 4 + e] = g[e];
}

// in-place softmax over fp16 scores (fp32 math in smem); per-batch expert skip
__global__ void softmax_hh_k(__half* __restrict__ P, int ncols,
                             const float* __restrict__ skipg, int eoff)
{
    int row = blockIdx.x;
    if (skipg && skipg[(row >> 14) * 4 + eoff] == 0.f) return;  // 16384 rows per batch
    __half* p = P + (long long)row * ncols;
    __shared__ float sm[1024];
    __shared__ float red[256];
    int tid = threadIdx.x;
    float mx = -1e30f;
    for (int c = tid; c < ncols; c += 256) { float v = __half2float(p[c]); sm[c] = v; mx = fmaxf(mx, v); }
    red[tid] = mx; __syncthreads();
    for (int st = 128; st > 0; st >>= 1) {
        if (tid < st) red[tid] = fmaxf(red[tid], red[tid + st]);
        __syncthreads();
    }
    mx = red[0]; __syncthreads();
    float sum = 0.f;
    for (int c = tid; c < ncols; c += 256) { float e = __expf(sm[c] - mx); sm[c] = e; sum += e; }
    red[tid] = sum; __syncthreads();
    for (int st = 128; st > 0; st >>= 1) {
        if (tid < st) red[tid] += red[tid + st];
        __syncthreads();
    }
    float inv = 1.f / red[0];
    __syncthreads();
    for (int c = tid; c < ncols; c += 256) p[c] = __float2half_rn(sm[c] * inv);
}

__global__ void x1_k(const float* __restrict__ xq, const float* __restrict__ delta,
                     const float* __restrict__ alpha1, float* __restrict__ x1)
{
    int idx = blockIdx.x * blockDim.x + threadIdx.x;
    if (idx >= MQ * DD) return;
    float s = 1.f / (1.f + expf(-alpha1[0]));
    x1[idx] = xq[idx] + s * delta[idx];
}

__global__ void rmsnorm_h_k(const float* __restrict__ X, const float* __restrict__ w,
                            __half* __restrict__ Y, int ncols)
{
    int row = blockIdx.x;
    const float* p = X + (long long)row * ncols;
    __half* q = Y + (long long)row * ncols;
    __shared__ float red[256];
    float s = 0.f;
    for (int c = threadIdx.x; c < ncols; c += 256) { float v = p[c]; s += v * v; }
    red[threadIdx.x] = s; __syncthreads();
    for (int st = 128; st > 0; st >>= 1) {
        if (threadIdx.x < st) red[threadIdx.x] += red[threadIdx.x + st];
        __syncthreads();
    }
    float scale = rsqrtf(red[0] / ncols + 1e-6f);
    __syncthreads();
    for (int c = threadIdx.x; c < ncols; c += 256) q[c] = __float2half_rn(w[c] * p[c] * scale);
}

__global__ void silu_add_h_k(const float* __restrict__ G, const float* __restrict__ U,
                             __half* __restrict__ Xd, long long n)
{
    long long idx = (long long)blockIdx.x * blockDim.x + threadIdx.x;
    if (idx >= n) return;
    float g = G[idx];
    Xd[idx] = __float2half_rn(g / (1.f + expf(-g)) + U[idx]);
}

__global__ void out_k(const float* __restrict__ x1, const float* __restrict__ T,
                      const float* __restrict__ alpha2, float* __restrict__ out)
{
    int idx = blockIdx.x * blockDim.x + threadIdx.x;
    if (idx >= MQ * DD) return;
    float s = 1.f / (1.f + expf(-alpha2[0]));
    out[idx] = x1[idx] + s * T[idx];
}

// ---------------------------------------------------------------------------
// Host helpers
// ---------------------------------------------------------------------------
static void hgemm(int OC, int M, int N, int K,
                  const __half* A, int lda, long long sA1, long long sA2,
                  const __half* B, int ldb, long long sB1, long long sB2,
                  void* C, int ldc, long long sC1, long long sC2,
                  int Z, int zdiv, float alpha, float beta, const float* bias,
                  const float* rowscale = nullptr, int rs_shift = 0, int rs_mul = 0, int rs_off = 0,
                  const float* skipg = nullptr, int smode = 0, int eoff = 0)
{
    dim3 grid((N + 127) / 128, (M + 127) / 128, Z);
    if (OC)
        hgemm_k<1><<<grid, NT, HG_SMEM>>>(M, N, K, A, lda, sA1, sA2, B, ldb, sB1, sB2,
                                          C, ldc, sC1, sC2, zdiv, alpha, beta, bias,
                                          rowscale, rs_shift, rs_mul, rs_off, skipg, smode, eoff);
    else
        hgemm_k<0><<<grid, NT, HG_SMEM>>>(M, N, K, A, lda, sA1, sA2, B, ldb, sB1, sB2,
                                          C, ldc, sC1, sC2, zdiv, alpha, beta, bias,
                                          rowscale, rs_shift, rs_mul, rs_off, skipg, smode, eoff);
}

template <typename T>
static T* sym(const void* s)
{
    void* p = nullptr;
    cudaGetSymbolAddress(&p, (const void*)s);
    return (T*)p;
}

static void f2h_copy(const float* src, __half* dst, long long n)
{
    long long n4 = n / 4;
    f2h_copy_k<<<(int)((n4 + 255) / 256), 256>>>(src, dst, n4);
}

static void transpose_f2h(const float* src, __half* dst, int R, int C, int batch)
{
    dim3 grid((C + 31) / 32, (R + 31) / 32, batch);
    transpose_f2h_k<<<grid, dim3(32, 8)>>>(src, dst, R, C, (long long)R * C);
}

static void transpose_h(const __half* src, __half* dst, int R, int C, int batch,
                        const float* skipg, int eoff)
{
    dim3 grid((C + 31) / 32, (R + 31) / 32, batch);
    transpose_h_k<<<grid, dim3(32, 8)>>>(src, dst, R, C, (long long)R * C, skipg, eoff);
}

// ---------------------------------------------------------------------------
// kernel_launch
// ---------------------------------------------------------------------------
extern "C" void kernel_launch(void* const* d_in, const int* in_sizes, int n_in,
                              void* d_out, int out_size)
{
    const float* x_q      = (const float*)d_in[0];
    const float* z_a      = (const float*)d_in[1];
    const float* z_v      = (const float*)d_in[2];
    const float* z_av     = (const float*)d_in[3];
    const float* ln1_w    = (const float*)d_in[4];
    const float* router_W = (const float*)d_in[5];
    const float* router_b = (const float*)d_in[6];
    const float* Wq       = (const float*)d_in[7];
    const float* bq       = (const float*)d_in[8];
    const float* Wk       = (const float*)d_in[9];
    const float* bk       = (const float*)d_in[10];
    const float* Wv       = (const float*)d_in[11];
    const float* bv       = (const float*)d_in[12];
    const float* Wo       = (const float*)d_in[13];
    const float* bo       = (const float*)d_in[14];
    const float* alpha1   = (const float*)d_in[15];
    const float* alpha2   = (const float*)d_in[16];
    const float* ln2_w    = (const float*)d_in[17];
    const float* gate_w   = (const float*)d_in[18];
    const float* up_w     = (const float*)d_in[19];
    const float* down_w   = (const float*)d_in[20];
    const float* la_gA    = (const float*)d_in[21];
    const float* la_gB    = (const float*)d_in[22];
    const float* la_uA    = (const float*)d_in[23];
    const float* la_uB    = (const float*)d_in[24];
    const float* la_dA    = (const float*)d_in[25];
    const float* la_dB    = (const float*)d_in[26];
    float* out = (float*)d_out;

    cudaFuncSetAttribute(hgemm_k<0>, cudaFuncAttributeMaxDynamicSharedMemorySize, HG_SMEM);
    cudaFuncSetAttribute(hgemm_k<1>, cudaFuncAttributeMaxDynamicSharedMemorySize, HG_SMEM);

    float* pRrms  = sym<float>(&g_rrms);
    float* pXbar  = sym<float>(&g_xbar);
    float* pLog   = sym<float>(&g_logits);
    float* pGate  = sym<float>(&g_gate);
    float* pDelta = sym<float>(&g_delta);
    float* pX1    = sym<float>(&g_x1);
    float* pG     = sym<float>(&g_G);
    float* pU     = sym<float>(&g_U);
    float* pT     = sym<float>(&g_T);
    __half* hZ   = sym<__half>(&g_hZ);
    __half* hW   = sym<__half>(&g_hW);
    __half* hM   = sym<__half>(&g_hM);
    __half* hLa  = sym<__half>(&g_hLa);
    __half* hQ   = sym<__half>(&g_hQ);
    __half* hK   = sym<__half>(&g_hK);
    __half* hV   = sym<__half>(&g_hV);
    __half* hVt  = sym<__half>(&g_hVt);
    __half* hO   = sym<__half>(&g_hO);
    __half* hH   = sym<__half>(&g_hH);
    __half* hP   = sym<__half>(&g_hP);
    __half* hXd  = sym<__half>(&g_hXd);
    __half* hLt  = sym<__half>(&g_hLt);

    const long long WSZ = (long long)3 * DD * DD;
    __half* tWqT = hW;            __half* tWkT = hW + WSZ;
    __half* tWvT = hW + 2 * WSZ;  __half* tWoT = hW + 3 * WSZ;
    const long long MSZ = (long long)DD * FFD;
    __half* tGwT = hM; __half* tUwT = hM + MSZ; __half* tDwT = hM + 2 * MSZ;
    const long long ZA = (long long)BB * 512 * DD;
    const long long ZAV = (long long)BB * 1024 * DD;
    __half* hZa  = hZ;
    __half* hZv  = hZ + ZA;
    __half* hZav = hZ + 2 * ZA;
    __half* hXq  = hZ + 2 * ZA + ZAV;
    __half* tgA = hLa;             __half* tgB = tgA + DD * RR;
    __half* tuA = tgB + RR * FFD;  __half* tuB = tuA + DD * RR;
    __half* tdA = tuB + RR * FFD;  __half* tdB = tdA + FFD * RR;

    // ---- operand conversions ----
    transpose_f2h(Wq, tWqT, DD, DD, 3);
    transpose_f2h(Wk, tWkT, DD, DD, 3);
    transpose_f2h(Wv, tWvT, DD, DD, 3);
    transpose_f2h(Wo, tWoT, DD, DD, 3);
    transpose_f2h(gate_w, tGwT, DD, FFD, 1);
    transpose_f2h(up_w,   tUwT, DD, FFD, 1);
    transpose_f2h(down_w, tDwT, FFD, DD, 1);
    transpose_f2h(la_gA, tgA, DD, RR, 1);
    transpose_f2h(la_gB, tgB, RR, FFD, 1);
    transpose_f2h(la_uA, tuA, DD, RR, 1);
    transpose_f2h(la_uB, tuB, RR, FFD, 1);
    transpose_f2h(la_dA, tdA, FFD, RR, 1);
    transpose_f2h(la_dB, tdB, RR, DD, 1);
    f2h_copy(z_a,  hZa,  ZA);
    f2h_copy(z_v,  hZv,  ZA);
    f2h_copy(z_av, hZav, ZAV);
    f2h_copy(x_q,  hXq,  ZAV);

    const int EW_B = (MQ * DD + 255) / 256;

    // ---- router (fp32 path on original inputs; must precede expert loop) ----
    rowrms_k<<<MQ, 256>>>(x_q, pRrms, DD);
    xbar_k<<<(BB * DD + 255) / 256, 256>>>(x_q, pRrms, ln1_w, pXbar);
    router_logits_k<<<BB * 4, 256>>>(pXbar, router_W, router_b, pLog);
    gate_k<<<1, 32>>>(pLog, pGate);

    // ---- experts (CTA-level skip where gate[b,e] == 0) ----
    const __half* hzs[3] = {hZa, hZv, hZav};
    const int     nks[3] = {512, 512, 1024};
    const float att_scale = 0.08838834764831843f;  // 1/sqrt(128)

    for (int e = 0; e < 3; e++) {
        const __half* hz = hzs[e];
        int NK = nks[e];
        int MZ = BB * NK;

        hgemm(1, MQ, DD, DD, hXq, DD, 0, 0, tWqT + (long long)e * DD * DD, DD, 0, 0,
              hQ, DD, 0, 0, 1, 1, 1.f, 0.f, bq + e * DD,
              nullptr, 0, 0, 0, pGate, NQL, e);
        hgemm(1, MZ, DD, DD, hz, DD, 0, 0, tWkT + (long long)e * DD * DD, DD, 0, 0,
              hK, DD, 0, 0, 1, 1, 1.f, 0.f, bk + e * DD,
              nullptr, 0, 0, 0, pGate, NK, e);
        hgemm(1, MZ, DD, DD, hz, DD, 0, 0, tWvT + (long long)e * DD * DD, DD, 0, 0,
              hV, DD, 0, 0, 1, 1, 1.f, 0.f, bv + e * DD,
              nullptr, 0, 0, 0, pGate, NK, e);

        transpose_h(hV, hVt, NK, DD, BB, pGate, e);

        // scores -> fp16 in hP (alpha folds 1/sqrt(dh))
        hgemm(1, NQL, NK, DHH,
              hQ, DD, (long long)NQL * DD, DHH,
              hK, DD, (long long)NK * DD, DHH,
              hP, NK, (long long)HH * NQL * NK, (long long)NQL * NK,
              BB * HH, HH, att_scale, 0.f, nullptr,
              nullptr, 0, 0, 0, pGate, -HH, e);

        softmax_hh_k<<<BB * HH * NQL, 256>>>(hP, NK, pGate, e);

        hgemm(1, NQL, DHH, NK,
              hP, NK, (long long)HH * NQL * NK, (long long)NQL * NK,
              hVt, NK, (long long)DD * NK, (long long)DHH * NK,
              hO, DD, (long long)NQL * DD, DHH,
              BB * HH, HH, 1.f, 0.f, nullptr,
              nullptr, 0, 0, 0, pGate, -HH, e);

        // Wo + fused gate rowscale; inactive CTAs contribute exact zero
        hgemm(0, MQ, DD, DD, hO, DD, 0, 0, tWoT + (long long)e * DD * DD, DD, 0, 0,
              pDelta, DD, 0, 0, 1, 1, 1.f, (e == 0) ? 0.f : 1.f, bo + e * DD,
              pGate, 10, 4, e, pGate, NQL, e);
    }

    // ---- x1 = x_q + sigmoid(alpha1)*delta ----
    x1_k<<<EW_B, 256>>>(x_q, pDelta, alpha1, pX1);

    // ---- MLP with LoRA ----
    rmsnorm_h_k<<<MQ, 256>>>(pX1, ln2_w, hH, DD);

    // gate path
    hgemm(0, MQ, FFD, DD, hH, DD, 0, 0, tGwT, DD, 0, 0, pG, FFD, 0, 0, 1, 1, 1.f, 0.f, nullptr);
    hgemm(1, MQ, RR, DD, hH, DD, 0, 0, tgA, DD, 0, 0, hLt, RR, 0, 0, 1, 1, 1.f, 0.f, nullptr);
    hgemm(0, MQ, FFD, RR, hLt, RR, 0, 0, tgB, RR, 0, 0, pG, FFD, 0, 0, 1, 1, LORA_SCALE, 1.f, nullptr);

    // up path
    hgemm(0, MQ, FFD, DD, hH, DD, 0, 0, tUwT, DD, 0, 0, pU, FFD, 0, 0, 1, 1, 1.f, 0.f, nullptr);
    hgemm(1, MQ, RR, DD, hH, DD, 0, 0, tuA, DD, 0, 0, hLt, RR, 0, 0, 1, 1, 1.f, 0.f, nullptr);
    hgemm(0, MQ, FFD, RR, hLt, RR, 0, 0, tuB, RR, 0, 0, pU, FFD, 0, 0, 1, 1, LORA_SCALE, 1.f, nullptr);

    // x_down = silu(gate) + up -> fp16
    {
        long long n = (long long)MQ * FFD;
        silu_add_h_k<<<(int)((n + 255) / 256), 256>>>(pG, pU, hXd, n);
    }

    // down path
    hgemm(0, MQ, DD, FFD, hXd, FFD, 0, 0, tDwT, FFD, 0, 0, pT, DD, 0, 0, 1, 1, 1.f, 0.f, nullptr);
    hgemm(1, MQ, RR, FFD, hXd, FFD, 0, 0, tdA, FFD, 0, 0, hLt, RR, 0, 0, 1, 1, 1.f, 0.f, nullptr);
    hgemm(0, MQ, DD, RR, hLt, RR, 0, 0, tdB, RR, 0, 0, pT, DD, 0, 0, 1, 1, LORA_SCALE, 1.f, nullptr);

    // out = x1 + sigmoid(alpha2)*mlp_out
    out_k<<<EW_B, 256>>>(pX1, pT, alpha2, out);
}